// round 2
// baseline (speedup 1.0000x reference)
#include <cuda_runtime.h>
#include <math.h>

// Problem constants
#define BB 2
#define NN 10000
#define HH 128
#define EE 128000
#define MM (BB*EE)          // 256000 rows
#define GDIM 384            // 3*H

// ---------------- scratch (device globals; no runtime allocation) -------------
__device__ float g_x0[(size_t)MM*128];       // gathered h_target
__device__ float g_x1[(size_t)MM*128];       // gathered h_source
__device__ float g_gi[(size_t)MM*384];       // x @ W_ih^T
__device__ float g_gh[(size_t)MM*384];       // h @ W_hh^T
__device__ float g_y0[(size_t)MM*256];       // layer0 out t=0 [f0|b0]
__device__ float g_y1[(size_t)MM*256];       // layer0 out t=1 [f1|b1]
__device__ float g_hh[(size_t)MM*256];       // layer1 out t=0 [f0'|b0']
__device__ float g_hb1[(size_t)MM*128];      // layer1 backward t=1 state
__device__ float g_logits[MM];               // (B,E) gelu logits
__device__ float g_av[MM];                   // (E,B) (l+g)/tau
__device__ float g_gum[MM];                  // (E,B) gumbel noise
__device__ unsigned g_mxh[NN*BB];
__device__ unsigned g_mxs[NN*BB];
__device__ float g_sh[NN*BB];
__device__ float g_ss[NN*BB];

// ---------------- helpers -----------------------------------------------------
__device__ __forceinline__ unsigned enc_f(float x) {
    unsigned u = __float_as_uint(x);
    return (u & 0x80000000u) ? ~u : (u | 0x80000000u);
}
__device__ __forceinline__ float dec_f(unsigned v) {
    return (v & 0x80000000u) ? __uint_as_float(v ^ 0x80000000u) : __uint_as_float(~v);
}
#define ENC_NEG_INF 0x007FFFFFu   // enc(-inf)

__device__ __forceinline__ float sigmoidf_(float x) { return 1.0f / (1.0f + expf(-x)); }

// ---------------- gather ------------------------------------------------------
__global__ void gather_kernel(const float4* __restrict__ h,
                              const int* __restrict__ tgt,
                              const int* __restrict__ src,
                              float4* __restrict__ x0, float4* __restrict__ x1) {
    long long idx = (long long)blockIdx.x * blockDim.x + threadIdx.x; // B*E*32
    int q = (int)(idx & 31);
    long long be = idx >> 5;                 // m = b*E + e
    int e = (int)(be % EE);
    int b = (int)(be / EE);
    int t = tgt[e], s = src[e];
    x0[be * 32 + q] = h[((long long)b * NN + t) * 32 + q];
    x1[be * 32 + q] = h[((long long)b * NN + s) * 32 + q];
}

// ---------------- SGEMM: C[M x 384] = A[M x K] * W^T (W is [384 x K]) ---------
#define BM 64
#define BN 64
#define BK 32
#define SPAD 68

__global__ void sgemm_nt(const float* __restrict__ A, int lda,
                         const float* __restrict__ W, int K,
                         float* __restrict__ C) {
    __shared__ float As[BK][SPAD];
    __shared__ float Bs[BK][SPAD];
    int tid = threadIdx.x;
    int rowBlk = blockIdx.y * BM;
    int colBlk = blockIdx.x * BN;
    int rg = tid & 15;
    int cg = tid >> 4;
    int r0 = rg * 4, c0 = cg * 8;
    float acc[4][8];
    #pragma unroll
    for (int i = 0; i < 4; i++)
        #pragma unroll
        for (int j = 0; j < 8; j++) acc[i][j] = 0.0f;

    int lrow = tid >> 3;            // 0..15
    int lcol4 = (tid & 7) * 4;      // 0,4,...,28

    for (int kt = 0; kt < K; kt += BK) {
        #pragma unroll
        for (int w = 0; w < 4; w++) {
            int r = lrow + w * 16;
            float4 v = *(const float4*)(A + (size_t)(rowBlk + r) * lda + kt + lcol4);
            As[lcol4 + 0][r] = v.x; As[lcol4 + 1][r] = v.y;
            As[lcol4 + 2][r] = v.z; As[lcol4 + 3][r] = v.w;
        }
        #pragma unroll
        for (int w = 0; w < 4; w++) {
            int r = lrow + w * 16;
            float4 v = *(const float4*)(W + (size_t)(colBlk + r) * K + kt + lcol4);
            Bs[lcol4 + 0][r] = v.x; Bs[lcol4 + 1][r] = v.y;
            Bs[lcol4 + 2][r] = v.z; Bs[lcol4 + 3][r] = v.w;
        }
        __syncthreads();
        #pragma unroll
        for (int k = 0; k < BK; k++) {
            float4 a4  = *(const float4*)&As[k][r0];
            float4 b4a = *(const float4*)&Bs[k][c0];
            float4 b4b = *(const float4*)&Bs[k][c0 + 4];
            float av[4] = {a4.x, a4.y, a4.z, a4.w};
            float bv[8] = {b4a.x, b4a.y, b4a.z, b4a.w, b4b.x, b4b.y, b4b.z, b4b.w};
            #pragma unroll
            for (int i = 0; i < 4; i++)
                #pragma unroll
                for (int j = 0; j < 8; j++)
                    acc[i][j] = fmaf(av[i], bv[j], acc[i][j]);
        }
        __syncthreads();
    }
    #pragma unroll
    for (int i = 0; i < 4; i++) {
        size_t row = (size_t)(rowBlk + r0 + i);
        #pragma unroll
        for (int j = 0; j < 8; j += 4) {
            float4 v = make_float4(acc[i][j], acc[i][j+1], acc[i][j+2], acc[i][j+3]);
            *(float4*)(C + row * GDIM + colBlk + c0 + j) = v;
        }
    }
}

// ---------------- GRU pointwise ------------------------------------------------
__global__ void gru_pointwise(const float* __restrict__ gi,
                              const float* __restrict__ gh,      // may be null (h_prev == 0)
                              const float* __restrict__ hp, int hp_stride, // may be null
                              const float* __restrict__ b_ih,
                              const float* __restrict__ b_hh,
                              float* __restrict__ out, int out_stride) {
    long long idx = (long long)blockIdx.x * blockDim.x + threadIdx.x; // M*128
    int j = (int)(idx & 127);
    long long m = idx >> 7;
    const float* gir = gi + m * GDIM;
    float ir = gir[j]        + b_ih[j];
    float iz = gir[128 + j]  + b_ih[128 + j];
    float in_ = gir[256 + j] + b_ih[256 + j];
    float hr, hz, hn;
    if (gh) {
        const float* ghr = gh + m * GDIM;
        hr = ghr[j]       + b_hh[j];
        hz = ghr[128 + j] + b_hh[128 + j];
        hn = ghr[256 + j] + b_hh[256 + j];
    } else {
        hr = b_hh[j]; hz = b_hh[128 + j]; hn = b_hh[256 + j];
    }
    float r = sigmoidf_(ir + hr);
    float z = sigmoidf_(iz + hz);
    float n = tanhf(in_ + r * hn);
    float hv = hp ? hp[m * (long long)hp_stride + j] : 0.0f;
    out[m * (long long)out_stride + j] = (1.0f - z) * n + z * hv;
}

// ---------------- logits: gelu( hh . w_con + b_con ) ---------------------------
__global__ void logits_kernel(const float* __restrict__ hh,
                              const float* __restrict__ w_con,
                              const float* __restrict__ b_con,
                              float* __restrict__ logits) {
    long long gth = (long long)blockIdx.x * blockDim.x + threadIdx.x;
    long long warp = gth >> 5;
    int lane = (int)(gth & 31);
    const float* row = hh + warp * 256;
    float s = 0.0f;
    #pragma unroll
    for (int k = 0; k < 8; k++) s = fmaf(row[lane + k * 32], w_con[lane + k * 32], s);
    #pragma unroll
    for (int o = 16; o > 0; o >>= 1) s += __shfl_xor_sync(0xFFFFFFFFu, s, o);
    if (lane == 0) {
        float x = s + b_con[0];
        logits[warp] = 0.5f * x * (1.0f + erff(x * 0.70710678118654752440f));
    }
}

// ---------------- JAX threefry2x32 gumbel, PARTITIONABLE mode ------------------
// jax >= 0.4.30 default: bits(i) = out0 ^ out1 where
// (out0, out1) = threefry2x32(key=(0,42), x0=hi32(i)=0, x1=lo32(i)=i)
__device__ __forceinline__ void threefry2x32_dev(unsigned k0, unsigned k1,
                                                 unsigned& x0, unsigned& x1) {
    unsigned ks2 = k0 ^ k1 ^ 0x1BD11BDAu;
    x0 += k0; x1 += k1;
#define TFR(r) { x0 += x1; x1 = (x1 << (r)) | (x1 >> (32 - (r))); x1 ^= x0; }
#define TFG(a, b, c, d, A0, A1, INC) TFR(a) TFR(b) TFR(c) TFR(d) x0 += (A0); x1 += (A1) + (INC);
    TFG(13, 15, 26, 6,  k1,  ks2, 1u)
    TFG(17, 29, 16, 24, ks2, k0,  2u)
    TFG(13, 15, 26, 6,  k0,  k1,  3u)
    TFG(17, 29, 16, 24, k1,  ks2, 4u)
    TFG(13, 15, 26, 6,  ks2, k0,  5u)
#undef TFR
#undef TFG
}

__device__ __forceinline__ float bits_to_gumbel(unsigned bits) {
    float u = __uint_as_float((bits >> 9) | 0x3f800000u) - 1.0f;
    float v = fmaxf(u, 1.175494350822287508e-38f);
    return -logf(-logf(v));
}

__global__ void gumbel_kernel(float* __restrict__ g) {
    int i = blockIdx.x * blockDim.x + threadIdx.x;  // 0..255999 flat (E,B) index
    if (i >= MM) return;
    unsigned x0 = 0u, x1 = (unsigned)i;
    threefry2x32_dev(0u, 42u, x0, x1);
    g[i] = bits_to_gumbel(x0 ^ x1);
}

// ---------------- init / segment softmax / scatter -----------------------------
__global__ void init_kernel(float* __restrict__ out,
                            unsigned* __restrict__ mxh, unsigned* __restrict__ mxs,
                            float* __restrict__ sh, float* __restrict__ ss) {
    int i = blockIdx.x * blockDim.x + threadIdx.x;
    if (i < BB * NN * HH) out[i] = 0.0f;
    if (i < NN * BB) { mxh[i] = ENC_NEG_INF; mxs[i] = ENC_NEG_INF; sh[i] = 0.0f; ss[i] = 0.0f; }
}

__global__ void prep_kernel(const float* __restrict__ logits, const float* __restrict__ g,
                            const int* __restrict__ src,
                            float* __restrict__ av,
                            unsigned* __restrict__ mxh, unsigned* __restrict__ mxs) {
    int f = blockIdx.x * blockDim.x + threadIdx.x;   // f = e*B + b, 256000 total
    int e = f >> 1, b = f & 1;
    float l = logits[(size_t)b * EE + e];
    float a = (l + g[f]) / 0.1f;
    av[f] = a;
    int n2 = src[e] * BB + b;
    atomicMax(&mxh[n2], enc_f(a));
    atomicMax(&mxs[n2], enc_f(l));
}

__global__ void sum_kernel(const float* __restrict__ logits, const float* __restrict__ av,
                           const int* __restrict__ src,
                           const unsigned* __restrict__ mxh, const unsigned* __restrict__ mxs,
                           float* __restrict__ sh, float* __restrict__ ss) {
    int f = blockIdx.x * blockDim.x + threadIdx.x;
    int e = f >> 1, b = f & 1;
    int n2 = src[e] * BB + b;
    atomicAdd(&sh[n2], expf(av[f] - dec_f(mxh[n2])));
    atomicAdd(&ss[n2], expf(logits[(size_t)b * EE + e] - dec_f(mxs[n2])));
}

__global__ void scatter_kernel(const float* __restrict__ h,
                               const int* __restrict__ tgt, const int* __restrict__ src,
                               const float* __restrict__ logits, const float* __restrict__ av,
                               const unsigned* __restrict__ mxh, const unsigned* __restrict__ mxs,
                               const float* __restrict__ sh, const float* __restrict__ ss,
                               float* __restrict__ out) {
    int e = blockIdx.x;
    int j = threadIdx.x;
    int s = src[e], t = tgt[e];
    #pragma unroll
    for (int b = 0; b < BB; b++) {
        int n2 = s * BB + b;
        float a = av[e * BB + b];
        float l = logits[(size_t)b * EE + e];
        float w = (expf(a - dec_f(mxh[n2])) / sh[n2]) * (expf(l - dec_f(mxs[n2])) / ss[n2]);
        float hv = h[((size_t)b * NN + s) * HH + j];
        atomicAdd(&out[((size_t)b * NN + t) * HH + j], hv * w);
    }
}

// ---------------- host orchestration -------------------------------------------
extern "C" void kernel_launch(void* const* d_in, const int* in_sizes, int n_in,
                              void* d_out, int out_size) {
    // Input index maps. Default: setup_inputs() insertion order. Fallback:
    // alphabetical key order (detected via in_sizes[0]: h has 2,560,000 elems;
    // alphabetical order starts with b_con, 1 elem).
    // order: h, ei, wih0f, whh0f, bih0f, bhh0f, wih0b, whh0b, bih0b, bhh0b,
    //        wih1f, whh1f, bih1f, bhh1f, wih1b, whh1b, bih1b, bhh1b, wcon, bcon
    static const int map_ins[20]   = {0,1,2,3,4,5,6,7,8,9,10,11,12,13,14,15,16,17,18,19};
    static const int map_alpha[20] = {10,9,17,13,6,2,16,12,5,1,19,15,8,4,18,14,7,3,11,0};
    const int* mp = (in_sizes[0] == BB * NN * HH) ? map_ins : map_alpha;

    const float* h   = (const float*)d_in[mp[0]];
    const int* ei    = (const int*)d_in[mp[1]];
    const int* tgt   = ei;            // edge_index[0]
    const int* src   = ei + EE;       // edge_index[1]
    const float* wih0f = (const float*)d_in[mp[2]];
    const float* whh0f = (const float*)d_in[mp[3]];
    const float* bih0f = (const float*)d_in[mp[4]];
    const float* bhh0f = (const float*)d_in[mp[5]];
    const float* wih0b = (const float*)d_in[mp[6]];
    const float* whh0b = (const float*)d_in[mp[7]];
    const float* bih0b = (const float*)d_in[mp[8]];
    const float* bhh0b = (const float*)d_in[mp[9]];
    const float* wih1f = (const float*)d_in[mp[10]];
    const float* bih1f = (const float*)d_in[mp[12]];
    const float* bhh1f = (const float*)d_in[mp[13]];
    const float* wih1b = (const float*)d_in[mp[14]];
    const float* whh1b = (const float*)d_in[mp[15]];
    const float* bih1b = (const float*)d_in[mp[16]];
    const float* bhh1b = (const float*)d_in[mp[17]];
    const float* wcon  = (const float*)d_in[mp[18]];
    const float* bcon  = (const float*)d_in[mp[19]];
    float* out = (float*)d_out;

    float *x0, *x1, *gi, *gh, *y0, *y1, *hhb, *hb1, *logits, *av, *gum;
    float *sh, *ss;
    unsigned *mxh, *mxs;
    cudaGetSymbolAddress((void**)&x0, g_x0);
    cudaGetSymbolAddress((void**)&x1, g_x1);
    cudaGetSymbolAddress((void**)&gi, g_gi);
    cudaGetSymbolAddress((void**)&gh, g_gh);
    cudaGetSymbolAddress((void**)&y0, g_y0);
    cudaGetSymbolAddress((void**)&y1, g_y1);
    cudaGetSymbolAddress((void**)&hhb, g_hh);
    cudaGetSymbolAddress((void**)&hb1, g_hb1);
    cudaGetSymbolAddress((void**)&logits, g_logits);
    cudaGetSymbolAddress((void**)&av, g_av);
    cudaGetSymbolAddress((void**)&gum, g_gum);
    cudaGetSymbolAddress((void**)&mxh, g_mxh);
    cudaGetSymbolAddress((void**)&mxs, g_mxs);
    cudaGetSymbolAddress((void**)&sh, g_sh);
    cudaGetSymbolAddress((void**)&ss, g_ss);

    dim3 gemmGrid(GDIM / BN, MM / BM);   // (6, 4000)
    const int PW_BLOCKS = (MM * 128) / 256;   // 128000

    // gather x0 (target), x1 (source)
    gather_kernel<<<(MM * 32) / 256, 256>>>((const float4*)h, tgt, src,
                                            (float4*)x0, (float4*)x1);

    // ---- layer 0 forward: f0 = cell(x0, 0) ; f1 = cell(x1, f0) ----
    sgemm_nt<<<gemmGrid, 128>>>(x0, 128, wih0f, 128, gi);
    gru_pointwise<<<PW_BLOCKS, 256>>>(gi, nullptr, nullptr, 0, bih0f, bhh0f, y0, 256);

    sgemm_nt<<<gemmGrid, 128>>>(x1, 128, wih0f, 128, gi);
    sgemm_nt<<<gemmGrid, 128>>>(y0, 256, whh0f, 128, gh);
    gru_pointwise<<<PW_BLOCKS, 256>>>(gi, gh, y0, 256, bih0f, bhh0f, y1, 256);

    // ---- layer 0 backward: b1 = cell(x1, 0) ; b0 = cell(x0, b1) ----
    sgemm_nt<<<gemmGrid, 128>>>(x1, 128, wih0b, 128, gi);
    gru_pointwise<<<PW_BLOCKS, 256>>>(gi, nullptr, nullptr, 0, bih0b, bhh0b, y1 + 128, 256);

    sgemm_nt<<<gemmGrid, 128>>>(x0, 128, wih0b, 128, gi);
    sgemm_nt<<<gemmGrid, 128>>>(y1 + 128, 256, whh0b, 128, gh);
    gru_pointwise<<<PW_BLOCKS, 256>>>(gi, gh, y1 + 128, 256, bih0b, bhh0b, y0 + 128, 256);

    // ---- layer 1: f0' = cellf(y0,0) ; b1' = cellb(y1,0) ; b0' = cellb(y0,b1')
    //      (f1' is never used downstream -> skipped)
    sgemm_nt<<<gemmGrid, 128>>>(y0, 256, wih1f, 256, gi);
    gru_pointwise<<<PW_BLOCKS, 256>>>(gi, nullptr, nullptr, 0, bih1f, bhh1f, hhb, 256);

    sgemm_nt<<<gemmGrid, 128>>>(y1, 256, wih1b, 256, gi);
    gru_pointwise<<<PW_BLOCKS, 256>>>(gi, nullptr, nullptr, 0, bih1b, bhh1b, hb1, 128);

    sgemm_nt<<<gemmGrid, 128>>>(y0, 256, wih1b, 256, gi);
    sgemm_nt<<<gemmGrid, 128>>>(hb1, 128, whh1b, 128, gh);
    gru_pointwise<<<PW_BLOCKS, 256>>>(gi, gh, hb1, 128, bih1b, bhh1b, hhb + 128, 256);

    // ---- logits, gumbel, segment softmaxes, weighted scatter ----
    logits_kernel<<<(MM * 32) / 256, 256>>>(hhb, wcon, bcon, logits);
    gumbel_kernel<<<(MM + 255) / 256, 256>>>(gum);
    init_kernel<<<(BB * NN * HH + 255) / 256, 256>>>(out, mxh, mxs, sh, ss);
    prep_kernel<<<MM / 256, 256>>>(logits, gum, src, av, mxh, mxs);
    sum_kernel<<<MM / 256, 256>>>(logits, av, src, mxh, mxs, sh, ss);
    scatter_kernel<<<EE, 128>>>(h, tgt, src, logits, av, mxh, mxs, sh, ss, out);
}